// round 16
// baseline (speedup 1.0000x reference)
#include <cuda_runtime.h>
#include <cuda_fp16.h>

#define N_NODES 50000
#define N_EDGES 800000
#define HID 64
#define N_LAYERS 3
#define N_GRAPHS 64
#define NB_NODES 196        // ceil(50000/256)
#define EB4 782             // ceil(800000/4/256)
#define CVB 6250            // N_NODES*32 float2 / 256
#define PERM_SZ (N_EDGES + 3 * N_NODES)
#define FULL 0xffffffffu
#define AST 72              // A/W tile row stride in halves (144B: 16B-aligned, conflict-free)
#define SAT_MASK 0x3FFFFFFFFFFULL   // low 42 bits

// ---------------- scratch (device globals; zero-initialized at module load) ----------------
// feature buffers have one extra all-zero row (index N_NODES) used as gather padding.
__device__ __half g_xh[(N_NODES + 1) * HID];
__device__ __half g_h0[(N_NODES + 1) * HID];
__device__ __half g_h1[(N_NODES + 1) * HID];
__device__ unsigned long long g_pack[N_NODES];  // (deg<<42)|fixedpoint(sattr); zero at entry
__device__ int    g_deg[N_NODES];        // written by k_scan1
__device__ float  g_sattr[N_NODES];      // written by k_scan1
__device__ int    g_rowptr[N_NODES];     // padded CSR offsets (multiples of 4)
__device__ int    g_fill[N_NODES];
__device__ __align__(16) int g_perm[PERM_SZ];
__device__ float  g_c1[N_LAYERS][HID];
__device__ float  g_c2[N_LAYERS][HID];
__device__ float  g_gsum[N_GRAPHS];      // zeroed in k_scan1
__device__ int    g_ctr[N_LAYERS];       // work-steal counters, zeroed in k_scan1

// ---------------- #1: edge pass 1 (packed deg|sattr atomic) + fp16 convert ----------------
__device__ __forceinline__ unsigned long long enc_edge(float a) {
    return (1ULL << 42) | (unsigned long long)(long long)llrintf((a + 8.0f) * 1048576.0f);
}
__global__ void k_pre(const int* __restrict__ ei, const float* __restrict__ ea,
                      const float* __restrict__ x) {
    if (blockIdx.x < EB4) {
        int p = blockIdx.x * 256 + threadIdx.x;
        int e = p * 4;
        if (e >= N_EDGES) return;
        int4   d4 = *(const int4*)  (ei + N_EDGES + e);
        float4 a4 = *(const float4*)(ea + e);
        atomicAdd(&g_pack[d4.x], enc_edge(a4.x));
        atomicAdd(&g_pack[d4.y], enc_edge(a4.y));
        atomicAdd(&g_pack[d4.z], enc_edge(a4.z));
        atomicAdd(&g_pack[d4.w], enc_edge(a4.w));
    } else {
        int i = (blockIdx.x - EB4) * 256 + threadIdx.x;   // float2 index
        if (i < N_NODES * 32) {
            float2 v = ((const float2*)x)[i];
            ((__half2*)g_xh)[i] = __floats2half2_rn(v.x, v.y);
        }
    }
}

// ---------------- #2: scan over PADDED degrees + unpack + pad-slot fill + constants ----------------
__global__ void __launch_bounds__(256) k_scan1(const float* __restrict__ ew,
                                               const float* __restrict__ eb,
                                               const float* __restrict__ nw) {
    const int b = blockIdx.x, tid = threadIdx.x;
    if (b == NB_NODES) {
        if (tid < N_GRAPHS) g_gsum[tid] = 0.f;
        if (tid < N_LAYERS) g_ctr[tid] = 0;
        if (tid >= N_LAYERS * HID) return;
        int l = tid / HID, h = tid % HID;
        float a = 0.f, c = 0.f;
        for (int k = 0; k < HID; k++) {
            float w = nw[(l * 2 * HID + HID + k) * HID + h];  // W2[k][h]
            a += ew[l * HID + k] * w;
            c += eb[l * HID + k] * w;
        }
        g_c1[l][h] = a;
        g_c2[l][h] = c;
        return;
    }

    __shared__ int sW[8];
    __shared__ int sBase;
    const int lane = tid & 31, w = tid >> 5;

    // prefix sum of padded degrees from packed array
    const ulonglong2* __restrict__ p2 = (const ulonglong2*)g_pack;
    const int nq = b * 128;          // u64 pairs in prefix
    int s = 0;
    for (int j = tid; j < nq; j += 256) {
        ulonglong2 v = p2[j];
        int d0 = (int)(v.x >> 42), d1 = (int)(v.y >> 42);
        s += ((d0 + 3) & ~3) + ((d1 + 3) & ~3);
    }
#pragma unroll
    for (int o = 16; o; o >>= 1) s += __shfl_down_sync(FULL, s, o);
    if (lane == 0) sW[w] = s;
    __syncthreads();
    if (tid == 0) {
        int t = 0;
#pragma unroll
        for (int j = 0; j < 8; j++) t += sW[j];
        sBase = t;
    }
    __syncthreads();
    const int base = sBase;
    __syncthreads();

    int i = b * 256 + tid;
    unsigned long long pk = (i < N_NODES) ? g_pack[i] : 0ULL;
    int v = (int)(pk >> 42);
    float sat = (float)((double)(pk & SAT_MASK) * (1.0 / 1048576.0) - 8.0 * (double)v);
    int pv = (v + 3) & ~3;
    int inc = pv;
#pragma unroll
    for (int o = 1; o < 32; o <<= 1) {
        int t = __shfl_up_sync(FULL, inc, o);
        if (lane >= o) inc += t;
    }
    if (lane == 31) sW[w] = inc;
    __syncthreads();
    int wo = 0;
    for (int j = 0; j < w; j++) wo += sW[j];
    int exc = base + wo + inc - pv;
    if (i < N_NODES) {
        g_deg[i] = v;
        g_sattr[i] = sat;
        g_rowptr[i] = exc;
        g_fill[i] = exc;
        for (int t = v; t < pv; t++) g_perm[exc + t] = N_NODES;  // pad -> zero row
    }
}

// ---------------- #3: edge pass 2: CSR bucket placement (4 edges/thread) ----------------
__global__ void k_edge2(const int* __restrict__ ei) {
    int p = blockIdx.x * blockDim.x + threadIdx.x;
    int e = p * 4;
    if (e >= N_EDGES) return;
    int4 s4 = *(const int4*)(ei + e);
    int4 d4 = *(const int4*)(ei + N_EDGES + e);
    g_perm[atomicAdd(&g_fill[d4.x], 1)] = s4.x;
    g_perm[atomicAdd(&g_fill[d4.y], 1)] = s4.y;
    g_perm[atomicAdd(&g_fill[d4.z], 1)] = s4.z;
    g_perm[atomicAdd(&g_fill[d4.w], 1)] = s4.w;
}

// ---------------- #4-6: fused layer: 16 nodes/task, full-M HMMA, 5 blk/SM ----------------
__global__ void __launch_bounds__(256, 5) k_layer(
    const __half* __restrict__ xin, __half* __restrict__ xout,
    const float* __restrict__ nw, const float* __restrict__ nb, int l,
    int last, const float* __restrict__ fcw, const int* __restrict__ batch)
{
    __shared__ __half sWh[HID * AST];       // Wt[h][k] fp16, stride 72 halves   9.2KB
    __shared__ __half sAh[8 * 16 * AST];    // per-warp A tile 16x64 (all real) 18.4KB
    __shared__ float  sC[4][HID];           // c1, c2, bias, fcw                 1KB
    const int tid = threadIdx.x;

    {   // stage W1 transposed fp16 + stage constants
        const float* __restrict__ nwl = nw + (size_t)l * 2 * HID * HID;
        for (int i = tid; i < HID * HID; i += 256) {
            int h = i & 63, k = i >> 6;
            sWh[h * AST + k] = __float2half(nwl[k * HID + h]);
        }
        if (tid < HID) {
            sC[0][tid] = g_c1[l][tid];
            sC[1][tid] = g_c2[l][tid];
            sC[2][tid] = nb[l * HID + tid];
            sC[3][tid] = fcw[tid];
        }
    }
    __syncthreads();

    const int warp = tid >> 5, lane = tid & 31;
    const int q = lane >> 3, c = lane & 7;   // quarter-warp id, col-block
    __half* __restrict__ sAw = sAh + warp * 16 * AST;
    const unsigned sA_base = (unsigned)__cvta_generic_to_shared(sAw);
    const unsigned sW_base = (unsigned)__cvta_generic_to_shared(sWh);
    const uint4* __restrict__ xh4 = (const uint4*)xin;   // 8 halves per lane

    for (;;) {
        int base;
        if (lane == 0) base = atomicAdd(&g_ctr[l], 16);
        base = __shfl_sync(FULL, base, 0);
        if (base >= N_NODES) break;       // 50000 % 16 == 0: full tasks only

        int bp = 0, dp = 0;
        if (lane < 16) {
            bp = g_rowptr[base + lane];
            dp = g_deg[base + lane];
        }

        // ---- gather: each quarter-warp owns nodes base+q+4h, h=0..3 ----
#pragma unroll
        for (int h = 0; h < 4; h++) {
            const int slot = q + 4 * h;
            const int bj = __shfl_sync(FULL, bp, slot);
            const int pd = (__shfl_sync(FULL, dp, slot) + 3) & ~3;

            __half2 z = __floats2half2_rn(0.f, 0.f);
            __half2 A0[4] = {z, z, z, z};
            __half2 A1[4] = {z, z, z, z};
            __half2 A2[4] = {z, z, z, z};
            __half2 A3[4] = {z, z, z, z};
            const int4* __restrict__ pB4 = (const int4*)(g_perm + bj);  // 16B aligned
#pragma unroll 2
            for (int i = 0; i < (pd >> 2); i++) {
                const int4 s4 = pB4[i];                 // one LDG.128: 4 indices
                const uint4 v0 = xh4[s4.x * 8 + c];
                const uint4 v1 = xh4[s4.y * 8 + c];
                const uint4 v2 = xh4[s4.z * 8 + c];
                const uint4 v3 = xh4[s4.w * 8 + c];
                A0[0] = __hadd2(A0[0], *(const __half2*)&v0.x);
                A0[1] = __hadd2(A0[1], *(const __half2*)&v0.y);
                A0[2] = __hadd2(A0[2], *(const __half2*)&v0.z);
                A0[3] = __hadd2(A0[3], *(const __half2*)&v0.w);
                A1[0] = __hadd2(A1[0], *(const __half2*)&v1.x);
                A1[1] = __hadd2(A1[1], *(const __half2*)&v1.y);
                A1[2] = __hadd2(A1[2], *(const __half2*)&v1.z);
                A1[3] = __hadd2(A1[3], *(const __half2*)&v1.w);
                A2[0] = __hadd2(A2[0], *(const __half2*)&v2.x);
                A2[1] = __hadd2(A2[1], *(const __half2*)&v2.y);
                A2[2] = __hadd2(A2[2], *(const __half2*)&v2.z);
                A2[3] = __hadd2(A2[3], *(const __half2*)&v2.w);
                A3[0] = __hadd2(A3[0], *(const __half2*)&v3.x);
                A3[1] = __hadd2(A3[1], *(const __half2*)&v3.y);
                A3[2] = __hadd2(A3[2], *(const __half2*)&v3.z);
                A3[3] = __hadd2(A3[3], *(const __half2*)&v3.w);
            }
            __half2 m0 = __hadd2(__hadd2(A0[0], A1[0]), __hadd2(A2[0], A3[0]));
            __half2 m1 = __hadd2(__hadd2(A0[1], A1[1]), __hadd2(A2[1], A3[1]));
            __half2 m2 = __hadd2(__hadd2(A0[2], A1[2]), __hadd2(A2[2], A3[2]));
            __half2 m3 = __hadd2(__hadd2(A0[3], A1[3]), __hadd2(A2[3], A3[3]));
            uint4 o;
            o.x = *(unsigned*)&m0;  o.y = *(unsigned*)&m1;
            o.z = *(unsigned*)&m2;  o.w = *(unsigned*)&m3;
            *(uint4*)&sAw[slot * AST + 8 * c] = o;      // fp16 row, STS.128
        }
        __syncwarp();

        // ---- epilogue constants per lane's two nodes ----
        const int r = lane >> 2;
        const int cb = 2 * (lane & 3);
        const float sa0 = g_sattr[base + r];
        const float sa1 = g_sattr[base + r + 8];
        const float dg0 = (float)__shfl_sync(FULL, dp, r);
        const float dg1 = (float)__shfl_sync(FULL, dp, r + 8);
        const int t = lane >> 3, rr = lane & 7;
        float s0 = 0.f, s1 = 0.f;

        // ---- MLP: two passes of 4 n-tiles (d[4][4] keeps regs low) ----
#pragma unroll
        for (int h2 = 0; h2 < 2; h2++) {
            float d[4][4];
#pragma unroll
            for (int nt = 0; nt < 4; nt++) {
                d[nt][0] = 0.f; d[nt][1] = 0.f; d[nt][2] = 0.f; d[nt][3] = 0.f;
            }
#pragma unroll
            for (int kt = 0; kt < 4; kt++) {
                unsigned a0, a1, a2, a3;
                const unsigned addrA = sA_base +
                    (((rr + ((t & 1) << 3)) * AST + kt * 16 + ((t >> 1) << 3)) << 1);
                asm volatile("ldmatrix.sync.aligned.m8n8.x4.shared.b16 {%0,%1,%2,%3}, [%4];"
                    : "=r"(a0), "=r"(a1), "=r"(a2), "=r"(a3) : "r"(addrA));
#pragma unroll
                for (int p = 0; p < 2; p++) {
                    const int pp = 2 * h2 + p;
                    unsigned b0, b1, b2, b3;
                    const unsigned addrB = sW_base +
                        ((((2 * pp + (t >> 1)) * 8 + rr) * AST + kt * 16 + ((t & 1) << 3)) << 1);
                    asm volatile("ldmatrix.sync.aligned.m8n8.x4.shared.b16 {%0,%1,%2,%3}, [%4];"
                        : "=r"(b0), "=r"(b1), "=r"(b2), "=r"(b3) : "r"(addrB));
                    asm volatile("mma.sync.aligned.m16n8k16.row.col.f32.f16.f16.f32 "
                        "{%0,%1,%2,%3}, {%4,%5,%6,%7}, {%8,%9}, {%0,%1,%2,%3};"
                        : "+f"(d[2*p][0]), "+f"(d[2*p][1]), "+f"(d[2*p][2]), "+f"(d[2*p][3])
                        : "r"(a0), "r"(a1), "r"(a2), "r"(a3), "r"(b0), "r"(b1));
                    asm volatile("mma.sync.aligned.m16n8k16.row.col.f32.f16.f16.f32 "
                        "{%0,%1,%2,%3}, {%4,%5,%6,%7}, {%8,%9}, {%0,%1,%2,%3};"
                        : "+f"(d[2*p+1][0]), "+f"(d[2*p+1][1]), "+f"(d[2*p+1][2]), "+f"(d[2*p+1][3])
                        : "r"(a0), "r"(a1), "r"(a2), "r"(a3), "r"(b2), "r"(b3));
                }
            }
            // ---- epilogue for this pass: n-tiles h2*4 .. h2*4+3 ----
#pragma unroll
            for (int nt = 0; nt < 4; nt++) {
                const int c0 = h2 * 32 + nt * 8 + cb;
                const float2 c1v = *(const float2*)&sC[0][c0];
                const float2 c2v = *(const float2*)&sC[1][c0];
                const float2 bv  = *(const float2*)&sC[2][c0];
                float u0 = d[nt][0] + sa0 * c1v.x + dg0 * c2v.x + bv.x;
                float u1 = d[nt][1] + sa0 * c1v.y + dg0 * c2v.y + bv.y;
                float w0 = d[nt][2] + sa1 * c1v.x + dg1 * c2v.x + bv.x;
                float w1 = d[nt][3] + sa1 * c1v.y + dg1 * c2v.y + bv.y;
                u0 = fmaxf(u0, 0.f);  u1 = fmaxf(u1, 0.f);   // ReLU
                w0 = fmaxf(w0, 0.f);  w1 = fmaxf(w1, 0.f);
                if (!last) {
                    ((__half2*)xout)[(base + r) * 32 + (c0 >> 1)]     = __floats2half2_rn(u0, u1);
                    ((__half2*)xout)[(base + r + 8) * 32 + (c0 >> 1)] = __floats2half2_rn(w0, w1);
                } else {
                    const float2 fv = *(const float2*)&sC[3][c0];
                    s0 += u0 * fv.x + u1 * fv.y;
                    s1 += w0 * fv.x + w1 * fv.y;
                }
            }
        }
        if (last) {
            s0 += __shfl_xor_sync(FULL, s0, 1);
            s0 += __shfl_xor_sync(FULL, s0, 2);
            s1 += __shfl_xor_sync(FULL, s1, 1);
            s1 += __shfl_xor_sync(FULL, s1, 2);
            if ((lane & 3) == 0) {
                atomicAdd(&g_gsum[batch[base + r]], s0);
                atomicAdd(&g_gsum[batch[base + r + 8]], s1);
            }
        }
        __syncwarp();
    }
}

// ---------------- #7: final output (block 0) + packed-scratch cleanup (blocks 1..) ----------------
__global__ void k_out(float* __restrict__ out, const float* __restrict__ fcb,
                      const int* __restrict__ batch) {
    if (blockIdx.x == 0) {
        int g = threadIdx.x;
        if (g >= N_GRAPHS) return;
        int lo = 0, hi = N_NODES;
        while (lo < hi) { int m = (lo + hi) >> 1; if (batch[m] < g) lo = m + 1; else hi = m; }
        int lo2 = lo, hi2 = N_NODES;
        while (lo2 < hi2) { int m = (lo2 + hi2) >> 1; if (batch[m] < g + 1) lo2 = m + 1; else hi2 = m; }
        float c = (float)(lo2 - lo);
        out[g] = g_gsum[g] / fmaxf(c, 1.f) + fcb[0];
    } else {
        int i = (blockIdx.x - 1) * 256 + threadIdx.x;
        if (i < N_NODES) g_pack[i] = 0ULL;
    }
}

// ---------------- launch ----------------
extern "C" void kernel_launch(void* const* d_in, const int* in_sizes, int n_in,
                              void* d_out, int out_size) {
    const float* x    = (const float*)d_in[0];
    const float* ea   = (const float*)d_in[1];
    const float* ew   = (const float*)d_in[2];
    const float* eb   = (const float*)d_in[3];
    const float* nw   = (const float*)d_in[4];
    const float* nb   = (const float*)d_in[5];
    const float* fcw  = (const float*)d_in[6];
    const float* fcb  = (const float*)d_in[7];
    const int*   ei   = (const int*)d_in[8];
    const int*   batch= (const int*)d_in[9];
    float* out = (float*)d_out;

    __half* xh; cudaGetSymbolAddress((void**)&xh, g_xh);
    __half* h0; cudaGetSymbolAddress((void**)&h0, g_h0);
    __half* h1; cudaGetSymbolAddress((void**)&h1, g_h1);

    k_pre  <<<EB4 + CVB, 256>>>(ei, ea, x);        // #1
    k_scan1<<<NB_NODES + 1, 256>>>(ew, eb, nw);    // #2
    k_edge2<<<EB4, 256>>>(ei);                     // #3

    const int LB = 740;                            // 5 blocks/SM, work-stealing
    k_layer<<<LB, 256>>>(xh, h0, nw, nb, 0, 0, fcw, batch);   // #4 -> profiled
    k_layer<<<LB, 256>>>(h0, h1, nw, nb, 1, 0, fcw, batch);   // #5
    k_layer<<<LB, 256>>>(h1, h0, nw, nb, 2, 1, fcw, batch);   // #6 fused pooling

    k_out<<<NB_NODES + 1, 256>>>(out, fcb, batch); // #7 output + cleanup
}

// round 17
// speedup vs baseline: 1.1026x; 1.1026x over previous
#include <cuda_runtime.h>
#include <cuda_fp16.h>

#define N_NODES 50000
#define N_EDGES 800000
#define HID 64
#define N_LAYERS 3
#define N_GRAPHS 64
#define NB_NODES 196        // ceil(50000/256)
#define EB4 782             // ceil(800000/4/256)
#define CVB 6250            // N_NODES*32 float2 / 256
#define PERM_SZ (N_EDGES + 3 * N_NODES)
#define FULL 0xffffffffu
#define AST 72              // A/W tile row stride in halves (144B: 16B-aligned, conflict-free)
#define SAT_MASK 0x3FFFFFFFFFFULL   // low 42 bits

// ---------------- scratch (device globals; zero-initialized at module load) ----------------
// feature buffers have one extra all-zero row (index N_NODES) used as gather padding.
__device__ __half g_xh[(N_NODES + 1) * HID];
__device__ __half g_h0[(N_NODES + 1) * HID];
__device__ __half g_h1[(N_NODES + 1) * HID];
__device__ unsigned long long g_pack[N_NODES];  // (deg<<42)|fixedpoint(sattr); zero at entry
__device__ int    g_deg[N_NODES];        // written by k_scan1
__device__ float  g_sattr[N_NODES];      // written by k_scan1
__device__ int    g_rowptr[N_NODES];     // padded CSR offsets (multiples of 4)
__device__ int    g_fill[N_NODES];
__device__ __align__(16) int g_perm[PERM_SZ];
__device__ float  g_c1[N_LAYERS][HID];
__device__ float  g_c2[N_LAYERS][HID];
__device__ float  g_gsum[N_GRAPHS];      // zeroed in k_scan1
__device__ int    g_ctr[N_LAYERS];       // work-steal counters, zeroed in k_scan1

// ---------------- #1: edge pass 1 (packed deg|sattr atomic) + fp16 convert ----------------
__device__ __forceinline__ unsigned long long enc_edge(float a) {
    return (1ULL << 42) | (unsigned long long)(long long)llrintf((a + 8.0f) * 1048576.0f);
}
__global__ void k_pre(const int* __restrict__ ei, const float* __restrict__ ea,
                      const float* __restrict__ x) {
    if (blockIdx.x < EB4) {
        int p = blockIdx.x * 256 + threadIdx.x;
        int e = p * 4;
        if (e >= N_EDGES) return;
        int4   d4 = *(const int4*)  (ei + N_EDGES + e);
        float4 a4 = *(const float4*)(ea + e);
        atomicAdd(&g_pack[d4.x], enc_edge(a4.x));
        atomicAdd(&g_pack[d4.y], enc_edge(a4.y));
        atomicAdd(&g_pack[d4.z], enc_edge(a4.z));
        atomicAdd(&g_pack[d4.w], enc_edge(a4.w));
    } else {
        int i = (blockIdx.x - EB4) * 256 + threadIdx.x;   // float2 index
        if (i < N_NODES * 32) {
            float2 v = ((const float2*)x)[i];
            ((__half2*)g_xh)[i] = __floats2half2_rn(v.x, v.y);
        }
    }
}

// ---------------- #2: scan over PADDED degrees + unpack + pad-slot fill + constants ----------------
__global__ void __launch_bounds__(256) k_scan1(const float* __restrict__ ew,
                                               const float* __restrict__ eb,
                                               const float* __restrict__ nw) {
    const int b = blockIdx.x, tid = threadIdx.x;
    if (b == NB_NODES) {
        if (tid < N_GRAPHS) g_gsum[tid] = 0.f;
        if (tid < N_LAYERS) g_ctr[tid] = 0;
        if (tid >= N_LAYERS * HID) return;
        int l = tid / HID, h = tid % HID;
        float a = 0.f, c = 0.f;
        for (int k = 0; k < HID; k++) {
            float w = nw[(l * 2 * HID + HID + k) * HID + h];  // W2[k][h]
            a += ew[l * HID + k] * w;
            c += eb[l * HID + k] * w;
        }
        g_c1[l][h] = a;
        g_c2[l][h] = c;
        return;
    }

    __shared__ int sW[8];
    __shared__ int sBase;
    const int lane = tid & 31, w = tid >> 5;

    // prefix sum of padded degrees from packed array
    const ulonglong2* __restrict__ p2 = (const ulonglong2*)g_pack;
    const int nq = b * 128;          // u64 pairs in prefix
    int s = 0;
    for (int j = tid; j < nq; j += 256) {
        ulonglong2 v = p2[j];
        int d0 = (int)(v.x >> 42), d1 = (int)(v.y >> 42);
        s += ((d0 + 3) & ~3) + ((d1 + 3) & ~3);
    }
#pragma unroll
    for (int o = 16; o; o >>= 1) s += __shfl_down_sync(FULL, s, o);
    if (lane == 0) sW[w] = s;
    __syncthreads();
    if (tid == 0) {
        int t = 0;
#pragma unroll
        for (int j = 0; j < 8; j++) t += sW[j];
        sBase = t;
    }
    __syncthreads();
    const int base = sBase;
    __syncthreads();

    int i = b * 256 + tid;
    unsigned long long pk = (i < N_NODES) ? g_pack[i] : 0ULL;
    int v = (int)(pk >> 42);
    float sat = (float)((double)(pk & SAT_MASK) * (1.0 / 1048576.0) - 8.0 * (double)v);
    int pv = (v + 3) & ~3;
    int inc = pv;
#pragma unroll
    for (int o = 1; o < 32; o <<= 1) {
        int t = __shfl_up_sync(FULL, inc, o);
        if (lane >= o) inc += t;
    }
    if (lane == 31) sW[w] = inc;
    __syncthreads();
    int wo = 0;
    for (int j = 0; j < w; j++) wo += sW[j];
    int exc = base + wo + inc - pv;
    if (i < N_NODES) {
        g_deg[i] = v;
        g_sattr[i] = sat;
        g_rowptr[i] = exc;
        g_fill[i] = exc;
        for (int t = v; t < pv; t++) g_perm[exc + t] = N_NODES;  // pad -> zero row
    }
}

// ---------------- #3: edge pass 2: CSR bucket placement (4 edges/thread) ----------------
__global__ void k_edge2(const int* __restrict__ ei) {
    int p = blockIdx.x * blockDim.x + threadIdx.x;
    int e = p * 4;
    if (e >= N_EDGES) return;
    int4 s4 = *(const int4*)(ei + e);
    int4 d4 = *(const int4*)(ei + N_EDGES + e);
    g_perm[atomicAdd(&g_fill[d4.x], 1)] = s4.x;
    g_perm[atomicAdd(&g_fill[d4.y], 1)] = s4.y;
    g_perm[atomicAdd(&g_fill[d4.z], 1)] = s4.z;
    g_perm[atomicAdd(&g_fill[d4.w], 1)] = s4.w;
}

// ---------------- #4-6: fused layer: 8 nodes/task HADD2 gather -> HMMA MLP (R14) ----------------
__global__ void __launch_bounds__(256, 4) k_layer(
    const __half* __restrict__ xin, __half* __restrict__ xout,
    const float* __restrict__ nw, const float* __restrict__ nb, int l,
    int last, const float* __restrict__ fcw, const int* __restrict__ batch)
{
    __shared__ __half sWh[HID * AST];       // Wt[h][k] fp16, stride 72 halves   9.2KB
    __shared__ __half sAh[8 * 16 * AST];    // per-warp A tile 16x64 (rows 8-15 zero) 18.4KB
    __shared__ float  sC[4][HID];           // c1, c2, bias, fcw                 1KB
    const int tid = threadIdx.x;

    {   // stage W1 transposed fp16 + zero A tiles + stage constants
        const float* __restrict__ nwl = nw + (size_t)l * 2 * HID * HID;
        for (int i = tid; i < HID * HID; i += 256) {
            int h = i & 63, k = i >> 6;
            sWh[h * AST + k] = __float2half(nwl[k * HID + h]);
        }
        for (int i = tid; i < 8 * 16 * AST / 2; i += 256)
            ((unsigned*)sAh)[i] = 0u;
        if (tid < HID) {
            sC[0][tid] = g_c1[l][tid];
            sC[1][tid] = g_c2[l][tid];
            sC[2][tid] = nb[l * HID + tid];
            sC[3][tid] = fcw[tid];
        }
    }
    __syncthreads();

    const int warp = tid >> 5, lane = tid & 31;
    const int q = lane >> 3, c = lane & 7;   // quarter-warp id, col-block
    __half* __restrict__ sAw = sAh + warp * 16 * AST;
    const unsigned sA_base = (unsigned)__cvta_generic_to_shared(sAw);
    const unsigned sW_base = (unsigned)__cvta_generic_to_shared(sWh);
    const uint4* __restrict__ xh4 = (const uint4*)xin;   // 8 halves per lane

    for (;;) {
        int base;
        if (lane == 0) base = atomicAdd(&g_ctr[l], 8);
        base = __shfl_sync(FULL, base, 0);
        if (base >= N_NODES) break;

        int bp = 0, dp = 0;
        if (lane < 8) {                      // base+lane always < N_NODES (50000 % 8 == 0)
            bp = g_rowptr[base + lane];
            dp = g_deg[base + lane];
        }

        // ---- gather: each quarter-warp owns nodes base+q and base+q+4 ----
#pragma unroll
        for (int half = 0; half < 2; half++) {
            const int slot = q + 4 * half;
            const int bj = __shfl_sync(FULL, bp, slot);
            const int pd = (__shfl_sync(FULL, dp, slot) + 3) & ~3;

            __half2 z = __floats2half2_rn(0.f, 0.f);
            __half2 A0[4] = {z, z, z, z};
            __half2 A1[4] = {z, z, z, z};
            __half2 A2[4] = {z, z, z, z};
            __half2 A3[4] = {z, z, z, z};
            const int4* __restrict__ pB4 = (const int4*)(g_perm + bj);  // 16B aligned
#pragma unroll 2
            for (int i = 0; i < (pd >> 2); i++) {
                const int4 s4 = pB4[i];                 // one LDG.128: 4 indices
                const uint4 v0 = xh4[s4.x * 8 + c];
                const uint4 v1 = xh4[s4.y * 8 + c];
                const uint4 v2 = xh4[s4.z * 8 + c];
                const uint4 v3 = xh4[s4.w * 8 + c];
                A0[0] = __hadd2(A0[0], *(const __half2*)&v0.x);
                A0[1] = __hadd2(A0[1], *(const __half2*)&v0.y);
                A0[2] = __hadd2(A0[2], *(const __half2*)&v0.z);
                A0[3] = __hadd2(A0[3], *(const __half2*)&v0.w);
                A1[0] = __hadd2(A1[0], *(const __half2*)&v1.x);
                A1[1] = __hadd2(A1[1], *(const __half2*)&v1.y);
                A1[2] = __hadd2(A1[2], *(const __half2*)&v1.z);
                A1[3] = __hadd2(A1[3], *(const __half2*)&v1.w);
                A2[0] = __hadd2(A2[0], *(const __half2*)&v2.x);
                A2[1] = __hadd2(A2[1], *(const __half2*)&v2.y);
                A2[2] = __hadd2(A2[2], *(const __half2*)&v2.z);
                A2[3] = __hadd2(A2[3], *(const __half2*)&v2.w);
                A3[0] = __hadd2(A3[0], *(const __half2*)&v3.x);
                A3[1] = __hadd2(A3[1], *(const __half2*)&v3.y);
                A3[2] = __hadd2(A3[2], *(const __half2*)&v3.z);
                A3[3] = __hadd2(A3[3], *(const __half2*)&v3.w);
            }
            __half2 m0 = __hadd2(__hadd2(A0[0], A1[0]), __hadd2(A2[0], A3[0]));
            __half2 m1 = __hadd2(__hadd2(A0[1], A1[1]), __hadd2(A2[1], A3[1]));
            __half2 m2 = __hadd2(__hadd2(A0[2], A1[2]), __hadd2(A2[2], A3[2]));
            __half2 m3 = __hadd2(__hadd2(A0[3], A1[3]), __hadd2(A2[3], A3[3]));
            uint4 o;
            o.x = *(unsigned*)&m0;  o.y = *(unsigned*)&m1;
            o.z = *(unsigned*)&m2;  o.w = *(unsigned*)&m3;
            *(uint4*)&sAw[slot * AST + 8 * c] = o;      // fp16 row, STS.128
        }
        __syncwarp();

        // ---- MLP: mma.sync m16n8k16 (rows 8-15 of A permanently zero) ----
        float d[8][4];
#pragma unroll
        for (int nt = 0; nt < 8; nt++) {
            d[nt][0] = 0.f; d[nt][1] = 0.f; d[nt][2] = 0.f; d[nt][3] = 0.f;
        }
        const int t = lane >> 3, rr = lane & 7;
#pragma unroll
        for (int kt = 0; kt < 4; kt++) {
            unsigned a0, a1, a2, a3;
            {
                const unsigned addrA = sA_base +
                    (((rr + ((t & 1) << 3)) * AST + kt * 16 + ((t >> 1) << 3)) << 1);
                asm volatile("ldmatrix.sync.aligned.m8n8.x4.shared.b16 {%0,%1,%2,%3}, [%4];"
                    : "=r"(a0), "=r"(a1), "=r"(a2), "=r"(a3) : "r"(addrA));
            }
#pragma unroll
            for (int p = 0; p < 4; p++) {
                unsigned b0, b1, b2, b3;
                const unsigned addrB = sW_base +
                    ((((2 * p + (t >> 1)) * 8 + rr) * AST + kt * 16 + ((t & 1) << 3)) << 1);
                asm volatile("ldmatrix.sync.aligned.m8n8.x4.shared.b16 {%0,%1,%2,%3}, [%4];"
                    : "=r"(b0), "=r"(b1), "=r"(b2), "=r"(b3) : "r"(addrB));
                asm volatile("mma.sync.aligned.m16n8k16.row.col.f32.f16.f16.f32 "
                    "{%0,%1,%2,%3}, {%4,%5,%6,%7}, {%8,%9}, {%0,%1,%2,%3};"
                    : "+f"(d[2*p][0]), "+f"(d[2*p][1]), "+f"(d[2*p][2]), "+f"(d[2*p][3])
                    : "r"(a0), "r"(a1), "r"(a2), "r"(a3), "r"(b0), "r"(b1));
                asm volatile("mma.sync.aligned.m16n8k16.row.col.f32.f16.f16.f32 "
                    "{%0,%1,%2,%3}, {%4,%5,%6,%7}, {%8,%9}, {%0,%1,%2,%3};"
                    : "+f"(d[2*p+1][0]), "+f"(d[2*p+1][1]), "+f"(d[2*p+1][2]), "+f"(d[2*p+1][3])
                    : "r"(a0), "r"(a1), "r"(a2), "r"(a3), "r"(b2), "r"(b3));
            }
        }

        // ---- epilogue: lane owns node base+(lane>>2), cols nt*8 + 2*(lane&3)+{0,1} ----
        {
            const int r = lane >> 2;
            const int node = base + r;
            const float sa = g_sattr[node];
            const float dg = (float)__shfl_sync(FULL, dp, r);
            const int cb = 2 * (lane & 3);
            if (!last) {
#pragma unroll
                for (int nt = 0; nt < 8; nt++) {
                    const int c0 = nt * 8 + cb;
                    const float2 c1v = *(const float2*)&sC[0][c0];
                    const float2 c2v = *(const float2*)&sC[1][c0];
                    const float2 bv  = *(const float2*)&sC[2][c0];
                    float u0 = d[nt][0] + sa * c1v.x + dg * c2v.x + bv.x;
                    float u1 = d[nt][1] + sa * c1v.y + dg * c2v.y + bv.y;
                    u0 = fmaxf(u0, 0.f);   // ReLU; LeakyReLU identity on >= 0
                    u1 = fmaxf(u1, 0.f);
                    ((__half2*)xout)[node * 32 + (c0 >> 1)] = __floats2half2_rn(u0, u1);
                }
            } else {
                float s = 0.f;
#pragma unroll
                for (int nt = 0; nt < 8; nt++) {
                    const int c0 = nt * 8 + cb;
                    const float2 c1v = *(const float2*)&sC[0][c0];
                    const float2 c2v = *(const float2*)&sC[1][c0];
                    const float2 bv  = *(const float2*)&sC[2][c0];
                    const float2 fv  = *(const float2*)&sC[3][c0];
                    float u0 = d[nt][0] + sa * c1v.x + dg * c2v.x + bv.x;
                    float u1 = d[nt][1] + sa * c1v.y + dg * c2v.y + bv.y;
                    u0 = fmaxf(u0, 0.f);
                    u1 = fmaxf(u1, 0.f);
                    s += u0 * fv.x + u1 * fv.y;
                }
                s += __shfl_xor_sync(FULL, s, 1);
                s += __shfl_xor_sync(FULL, s, 2);
                if ((lane & 3) == 0) atomicAdd(&g_gsum[batch[node]], s);
            }
        }
    }
}

// ---------------- #7: final output (block 0) + packed-scratch cleanup (blocks 1..) ----------------
__global__ void k_out(float* __restrict__ out, const float* __restrict__ fcb,
                      const int* __restrict__ batch) {
    if (blockIdx.x == 0) {
        int g = threadIdx.x;
        if (g >= N_GRAPHS) return;
        int lo = 0, hi = N_NODES;
        while (lo < hi) { int m = (lo + hi) >> 1; if (batch[m] < g) lo = m + 1; else hi = m; }
        int lo2 = lo, hi2 = N_NODES;
        while (lo2 < hi2) { int m = (lo2 + hi2) >> 1; if (batch[m] < g + 1) lo2 = m + 1; else hi2 = m; }
        float c = (float)(lo2 - lo);
        out[g] = g_gsum[g] / fmaxf(c, 1.f) + fcb[0];
    } else {
        int i = (blockIdx.x - 1) * 256 + threadIdx.x;
        if (i < N_NODES) g_pack[i] = 0ULL;
    }
}

// ---------------- launch ----------------
extern "C" void kernel_launch(void* const* d_in, const int* in_sizes, int n_in,
                              void* d_out, int out_size) {
    const float* x    = (const float*)d_in[0];
    const float* ea   = (const float*)d_in[1];
    const float* ew   = (const float*)d_in[2];
    const float* eb   = (const float*)d_in[3];
    const float* nw   = (const float*)d_in[4];
    const float* nb   = (const float*)d_in[5];
    const float* fcw  = (const float*)d_in[6];
    const float* fcb  = (const float*)d_in[7];
    const int*   ei   = (const int*)d_in[8];
    const int*   batch= (const int*)d_in[9];
    float* out = (float*)d_out;

    __half* xh; cudaGetSymbolAddress((void**)&xh, g_xh);
    __half* h0; cudaGetSymbolAddress((void**)&h0, g_h0);
    __half* h1; cudaGetSymbolAddress((void**)&h1, g_h1);

    k_pre  <<<EB4 + CVB, 256>>>(ei, ea, x);        // #1
    k_scan1<<<NB_NODES + 1, 256>>>(ew, eb, nw);    // #2
    k_edge2<<<EB4, 256>>>(ei);                     // #3

    const int LB = 592;                            // 4 blocks/SM, work-stealing
    k_layer<<<LB, 256>>>(xh, h0, nw, nb, 0, 0, fcw, batch);   // #4 -> profiled
    k_layer<<<LB, 256>>>(h0, h1, nw, nb, 1, 0, fcw, batch);   // #5
    k_layer<<<LB, 256>>>(h1, h0, nw, nb, 2, 1, fcw, batch);   // #6 fused pooling

    k_out<<<NB_NODES + 1, 256>>>(out, fcb, batch); // #7 output + cleanup
}